// round 1
// baseline (speedup 1.0000x reference)
#include <cuda_runtime.h>
#include <math.h>

// Problem constants
#define BB 4
#define LL 2048
#define DDIM 1024
#define HH 16
#define DH 64
#define CH 128
#define NC 16
#define BH (BB*HH)        // 64
#define BLROWS (BB*LL)    // 8192

// ---------------- scratch (no allocations allowed) ----------------
__device__ float g_q[BB*HH*LL*DH];        // (B,H,L,d)
__device__ float g_k[BB*HH*LL*DH];
__device__ float g_v[BB*HH*LL*DH];
__device__ float g_att[BB*LL*DDIM];       // (B,L,D)
__device__ float g_S[BB*HH*NC*DH*DH];     // per-chunk kv, then exclusive prefix
__device__ float g_z[BB*HH*NC*DH];        // per-chunk ksum, then exclusive prefix

// ---------------- GEMM: C = A @ W^T + bias, optional silu, optional (B,H,L,d) layout ----------------
// A: (M,K) row-major, W: (N,K) row-major. M=8192, N=1024, K=1024 here.
// 128x128 block tile, 8x8 per thread, BK=16, 256 threads.
__global__ __launch_bounds__(256) void gemm_nt(
    const float* __restrict__ A, const float* __restrict__ W,
    const float* __restrict__ bias, float* __restrict__ C,
    int M, int N, int K, int dosilu, int attlay)
{
    __shared__ float As[16][132];
    __shared__ float Ws[16][132];

    const int t  = threadIdx.x;
    const int ty = t >> 4;        // 0..15
    const int tx = t & 15;        // 0..15
    const int m0 = blockIdx.y * 128;
    const int n0 = blockIdx.x * 128;

    const float* Ap = A + (size_t)m0 * K;
    const float* Wp = W + (size_t)n0 * K;

    float acc[8][8];
#pragma unroll
    for (int i = 0; i < 8; ++i)
#pragma unroll
        for (int j = 0; j < 8; ++j) acc[i][j] = 0.f;

    for (int k0 = 0; k0 < K; k0 += 16) {
#pragma unroll
        for (int r = 0; r < 2; ++r) {
            int f   = t * 2 + r;        // 0..511 float4 slots
            int row = f >> 2;           // 0..127
            int kk  = (f & 3) * 4;
            float4 av = *(const float4*)(Ap + (size_t)row * K + k0 + kk);
            As[kk+0][row] = av.x; As[kk+1][row] = av.y;
            As[kk+2][row] = av.z; As[kk+3][row] = av.w;
            float4 wv = *(const float4*)(Wp + (size_t)row * K + k0 + kk);
            Ws[kk+0][row] = wv.x; Ws[kk+1][row] = wv.y;
            Ws[kk+2][row] = wv.z; Ws[kk+3][row] = wv.w;
        }
        __syncthreads();

#pragma unroll
        for (int kk = 0; kk < 16; ++kk) {
            float a[8], b[8];
            *(float4*)(a)     = *(const float4*)&As[kk][ty*8];
            *(float4*)(a + 4) = *(const float4*)&As[kk][ty*8 + 4];
            *(float4*)(b)     = *(const float4*)&Ws[kk][tx*8];
            *(float4*)(b + 4) = *(const float4*)&Ws[kk][tx*8 + 4];
#pragma unroll
            for (int i = 0; i < 8; ++i)
#pragma unroll
                for (int j = 0; j < 8; ++j)
                    acc[i][j] = fmaf(a[i], b[j], acc[i][j]);
        }
        __syncthreads();
    }

#pragma unroll
    for (int i = 0; i < 8; ++i) {
        int m = m0 + ty*8 + i;
#pragma unroll
        for (int j = 0; j < 8; ++j) {
            int nn = n0 + tx*8 + j;
            float c = acc[i][j] + bias[nn];
            if (dosilu) c = c / (1.f + expf(-c));   // silu
            if (attlay) {
                // (B,L,D) row m -> (B,H,L,d)
                int b  = m >> 11;       // /2048 (L)
                int l  = m & 2047;
                int h  = nn >> 6;       // /64
                int dd = nn & 63;
                C[(((size_t)(b*HH + h))*LL + l)*DH + dd] = c;
            } else {
                C[(size_t)m * N + nn] = c;
            }
        }
    }
}

// ---------------- Phase A: per-chunk kv outer product + ksum ----------------
// grid = BH*NC blocks; block computes kv[64][64] = k_c^T @ v_c and ksum[64].
__global__ __launch_bounds__(256) void chunk_stats()
{
    __shared__ float ks[32*64];
    __shared__ float vs[32*64];

    const int bid = blockIdx.x;                  // bh*NC + n
    const float* kb = g_k + (size_t)bid * (CH*DH);
    const float* vb = g_v + (size_t)bid * (CH*DH);
    const int t  = threadIdx.x;
    const int td = t >> 4;       // 0..15 -> d rows td*4..
    const int te = t & 15;       // 0..15 -> e cols te*4..

    float acc[4][4];
#pragma unroll
    for (int i = 0; i < 4; ++i)
#pragma unroll
        for (int j = 0; j < 4; ++j) acc[i][j] = 0.f;
    float zacc = 0.f;

    for (int cb = 0; cb < 4; ++cb) {
#pragma unroll
        for (int r = 0; r < 2; ++r) {
            int f = t*2 + r;     // 0..511
            *(float4*)&ks[f*4] = *(const float4*)(kb + cb*2048 + f*4);
            *(float4*)&vs[f*4] = *(const float4*)(vb + cb*2048 + f*4);
        }
        __syncthreads();
#pragma unroll 8
        for (int c = 0; c < 32; ++c) {
            float a[4], b[4];
            *(float4*)a = *(const float4*)&ks[c*64 + td*4];
            *(float4*)b = *(const float4*)&vs[c*64 + te*4];
#pragma unroll
            for (int i = 0; i < 4; ++i)
#pragma unroll
                for (int j = 0; j < 4; ++j)
                    acc[i][j] = fmaf(a[i], b[j], acc[i][j]);
        }
        if (t < 64) {
#pragma unroll 8
            for (int c = 0; c < 32; ++c) zacc += ks[c*64 + t];
        }
        __syncthreads();
    }

    float* Sp = g_S + (size_t)bid * (DH*DH);
#pragma unroll
    for (int i = 0; i < 4; ++i)
#pragma unroll
        for (int j = 0; j < 4; ++j)
            Sp[(td*4 + i)*DH + te*4 + j] = acc[i][j];
    if (t < 64) g_z[(size_t)bid*DH + t] = zacc;
}

// ---------------- Phase B: exclusive scan over chunks, per (b,h) ----------------
__global__ __launch_bounds__(256) void scan_chunks()
{
    const int bh = blockIdx.x;
    const int t  = threadIdx.x;
    for (int idx = t; idx < DH*DH; idx += 256) {
        float accv = 0.f;
#pragma unroll
        for (int nn = 0; nn < NC; ++nn) {
            float* p = g_S + ((size_t)(bh*NC + nn))*(DH*DH) + idx;
            float tv = *p; *p = accv; accv += tv;
        }
    }
    if (t < DH) {
        float accv = 0.f;
#pragma unroll
        for (int nn = 0; nn < NC; ++nn) {
            float* p = g_z + ((size_t)(bh*NC + nn))*DH + t;
            float tv = *p; *p = accv; accv += tv;
        }
    }
}

// ---------------- Phase C: intra-chunk causal attention + state contribution ----------------
// grid = BH*NC. Per block: scores = tril(q k^T); den = rowsum(scores) + q.z;
// out = (scores @ v + q @ S) / max(den, eps)
#define SMEMC_FLOATS (64*136 + 64*136 + 128*64 + 64*64 + 64 + 128 + 128*132)
__global__ __launch_bounds__(256) void intra_chunk()
{
    extern __shared__ float sm[];
    float* qT   = sm;                 // [64][136] (c-major, padded)
    float* kT   = qT + 64*136;
    float* vs   = kT + 64*136;        // [128][64]
    float* Ss   = vs + 128*64;        // [64][64]
    float* zs   = Ss + 64*64;         // [64]
    float* rden = zs + 64;            // [128]
    float* ms   = rden + 128;         // [128][132]

    const int bid = blockIdx.x;       // bh*NC + n
    const int t   = threadIdx.x;
    const float* qb = g_q + (size_t)bid * (CH*DH);
    const float* kb = g_k + (size_t)bid * (CH*DH);
    const float* vb = g_v + (size_t)bid * (CH*DH);

    // load q,k transposed (dd-major)
    {
        int dd = t & 63;
        int ih = t >> 6;              // 0..3
#pragma unroll 8
        for (int ii = 0; ii < 32; ++ii) {
            int i = ih*32 + ii;
            qT[dd*136 + i] = qb[i*DH + dd];
            kT[dd*136 + i] = kb[i*DH + dd];
        }
    }
#pragma unroll
    for (int r = 0; r < 8; ++r) {
        int f = t + 256*r;
        *(float4*)&vs[f*4] = *(const float4*)(vb + f*4);
    }
    {
        const float* Sp = g_S + (size_t)bid * (DH*DH);
#pragma unroll
        for (int r = 0; r < 4; ++r) {
            int f = t + 256*r;
            *(float4*)&Ss[f*4] = *(const float4*)(Sp + f*4);
        }
    }
    if (t < 64) zs[t] = g_z[(size_t)bid*DH + t];
    __syncthreads();

    const int ty = t >> 4, tx = t & 15;
    const int i0 = ty*8, j0 = tx*8;

    // stage 1: scores tile (8x8)
    float acc[8][8];
#pragma unroll
    for (int i = 0; i < 8; ++i)
#pragma unroll
        for (int j = 0; j < 8; ++j) acc[i][j] = 0.f;

    if (j0 <= i0 + 7) {               // skip fully-masked tiles
#pragma unroll 4
        for (int c = 0; c < 64; ++c) {
            float a[8], b[8];
            *(float4*)(a)     = *(const float4*)&qT[c*136 + i0];
            *(float4*)(a + 4) = *(const float4*)&qT[c*136 + i0 + 4];
            *(float4*)(b)     = *(const float4*)&kT[c*136 + j0];
            *(float4*)(b + 4) = *(const float4*)&kT[c*136 + j0 + 4];
#pragma unroll
            for (int i = 0; i < 8; ++i)
#pragma unroll
                for (int j = 0; j < 8; ++j)
                    acc[i][j] = fmaf(a[i], b[j], acc[i][j]);
        }
    }
    // causal mask (j <= i keeps) + write scores
#pragma unroll
    for (int i = 0; i < 8; ++i)
#pragma unroll
        for (int j = 0; j < 8; ++j)
            ms[(i0+i)*132 + j0 + j] = (j0 + j <= i0 + i) ? acc[i][j] : 0.f;
    __syncthreads();

    // stage 1.5: denominator per row = rowsum(masked scores) + q.z
    if (t < 128) {
        int i = t;
        float s = 0.f;
#pragma unroll 8
        for (int j = 0; j < 128; ++j) s += ms[i*132 + j];
#pragma unroll 8
        for (int dd = 0; dd < 64; ++dd) s += qT[dd*136 + i] * zs[dd];
        rden[i] = 1.f / fmaxf(s, 0.001f);
    }
    __syncthreads();

    // stage 2: out[i][e] = sum_j ms[i][j]*v[j][e] + sum_dd q[i][dd]*S[dd][e]
    const int e0 = tx*4;
    float o[8][4];
#pragma unroll
    for (int i = 0; i < 8; ++i)
#pragma unroll
        for (int e = 0; e < 4; ++e) o[i][e] = 0.f;

#pragma unroll 4
    for (int j = 0; j < 128; ++j) {
        float vf[4];
        *(float4*)vf = *(const float4*)&vs[j*64 + e0];
#pragma unroll
        for (int i = 0; i < 8; ++i) {
            float mv = ms[(i0+i)*132 + j];
            o[i][0] = fmaf(mv, vf[0], o[i][0]);
            o[i][1] = fmaf(mv, vf[1], o[i][1]);
            o[i][2] = fmaf(mv, vf[2], o[i][2]);
            o[i][3] = fmaf(mv, vf[3], o[i][3]);
        }
    }
#pragma unroll 4
    for (int dd = 0; dd < 64; ++dd) {
        float sf[4];
        *(float4*)sf = *(const float4*)&Ss[dd*64 + e0];
#pragma unroll
        for (int i = 0; i < 8; ++i) {
            float qv = qT[dd*136 + i0 + i];
            o[i][0] = fmaf(qv, sf[0], o[i][0]);
            o[i][1] = fmaf(qv, sf[1], o[i][1]);
            o[i][2] = fmaf(qv, sf[2], o[i][2]);
            o[i][3] = fmaf(qv, sf[3], o[i][3]);
        }
    }

    // write to (B,L,D) layout for the output GEMM
    const int bh = bid >> 4, n = bid & 15;
    const int b = bh >> 4, h = bh & 15;
#pragma unroll
    for (int i = 0; i < 8; ++i) {
        float rd = rden[i0 + i];
        int l = n*CH + i0 + i;
#pragma unroll
        for (int e = 0; e < 4; ++e)
            g_att[((size_t)(b*LL + l))*DDIM + h*DH + e0 + e] = o[i][e] * rd;
    }
}

// ---------------- launch ----------------
extern "C" void kernel_launch(void* const* d_in, const int* in_sizes, int n_in,
                              void* d_out, int out_size)
{
    const float* x  = (const float*)d_in[0];
    const float* Wq = (const float*)d_in[1];
    const float* bq = (const float*)d_in[2];
    const float* Wk = (const float*)d_in[3];
    const float* bk = (const float*)d_in[4];
    const float* Wv = (const float*)d_in[5];
    const float* bv = (const float*)d_in[6];
    const float* Wo = (const float*)d_in[7];
    const float* bo = (const float*)d_in[8];
    float* out = (float*)d_out;

    float *qp, *kp, *vp, *attp;
    cudaGetSymbolAddress((void**)&qp,  g_q);
    cudaGetSymbolAddress((void**)&kp,  g_k);
    cudaGetSymbolAddress((void**)&vp,  g_v);
    cudaGetSymbolAddress((void**)&attp, g_att);

    dim3 gg(DDIM/128, BLROWS/128);   // (8, 64)
    dim3 bb(256);

    gemm_nt<<<gg, bb>>>(x, Wq, bq, qp, BLROWS, DDIM, DDIM, 1, 1);
    gemm_nt<<<gg, bb>>>(x, Wk, bk, kp, BLROWS, DDIM, DDIM, 1, 1);
    gemm_nt<<<gg, bb>>>(x, Wv, bv, vp, BLROWS, DDIM, DDIM, 0, 1);

    chunk_stats<<<BH*NC, 256>>>();
    scan_chunks<<<BH, 256>>>();

    static int smem_set = 0;
    (void)smem_set;
    cudaFuncSetAttribute(intra_chunk, cudaFuncAttributeMaxDynamicSharedMemorySize,
                         SMEMC_FLOATS * (int)sizeof(float));
    intra_chunk<<<BH*NC, 256, SMEMC_FLOATS * sizeof(float)>>>();

    gemm_nt<<<gg, bb>>>(attp, Wo, bo, out, BLROWS, DDIM, DDIM, 0, 0);
}

// round 4
// speedup vs baseline: 1.6306x; 1.6306x over previous
#include <cuda_runtime.h>
#include <cstdint>
#include <math.h>

// Problem constants
#define BB 4
#define LL 2048
#define DDIM 1024
#define HH 16
#define DH 64
#define CH 128
#define NC 16
#define BH (BB*HH)        // 64
#define BLROWS (BB*LL)    // 8192

// ---------------- scratch (no allocations allowed) ----------------
__device__ float g_q[BB*HH*LL*DH];        // (B,H,L,d)
__device__ float g_k[BB*HH*LL*DH];
__device__ float g_v[BB*HH*LL*DH];
__device__ float g_att[BB*LL*DDIM];       // (B,L,D)
__device__ float g_S[BB*HH*NC*DH*DH];
__device__ float g_z[BB*HH*NC*DH];

// =======================================================================
// 3xTF32 mma.sync GEMM:  C = A @ W^T + bias (A: M x K, W: N x K, row-major)
// Tile 128x128, BK=32, 3-stage cp.async pipeline, 8 warps (2x4), warp 64x32.
// Each input split hi/lo (Markidis): acc += hi*lo + lo*hi + hi*hi  (~21-bit mantissa)
// =======================================================================
#define BM 128
#define BN 128
#define BKK 32
#define KCH (DDIM/BKK)        // 32
#define GSTAGES 3
#define STRD 36               // floats per row (stride % 32 == 4 -> conflict-free frags)
#define A_FLOATS (BM*STRD)    // 4608
#define STAGE_FLOATS (2*A_FLOATS)   // 9216 (A then B)
#define SMEM_GEMM_BYTES (GSTAGES*STAGE_FLOATS*4)   // 110592

__device__ __forceinline__ void cp16(uint32_t dst, const void* src) {
    asm volatile("cp.async.cg.shared.global [%0], [%1], 16;" :: "r"(dst), "l"(src));
}
__device__ __forceinline__ uint32_t smem_u32(const void* p) {
    uint32_t a;
    asm("{ .reg .u64 t; cvta.to.shared.u64 t, %1; cvt.u32.u64 %0, t; }" : "=r"(a) : "l"(p));
    return a;
}
__device__ __forceinline__ void cp_commit() {
    asm volatile("cp.async.commit_group;");
}
#define CP_WAIT(n) asm volatile("cp.async.wait_group %0;" :: "n"(n))

__device__ __forceinline__ uint32_t to_tf32(float f) {
    uint32_t r;
    asm("cvt.rna.tf32.f32 %0, %1;" : "=r"(r) : "f"(f));
    return r;
}
// split f into tf32 hi + tf32 lo
__device__ __forceinline__ void split_tf32(float f, uint32_t& hi, uint32_t& lo) {
    hi = to_tf32(f);
    lo = to_tf32(f - __uint_as_float(hi));
}
__device__ __forceinline__ void mma8(float* d, const uint32_t* a, const uint32_t* b) {
    asm volatile(
        "mma.sync.aligned.m16n8k8.row.col.f32.tf32.tf32.f32 "
        "{%0,%1,%2,%3}, {%4,%5,%6,%7}, {%8,%9}, {%0,%1,%2,%3};"
        : "+f"(d[0]), "+f"(d[1]), "+f"(d[2]), "+f"(d[3])
        : "r"(a[0]), "r"(a[1]), "r"(a[2]), "r"(a[3]), "r"(b[0]), "r"(b[1]));
}

// grid: (DDIM/BN, BLROWS/BM) = (8, 64), 256 threads
__global__ void __launch_bounds__(256, 2) gemm_tc(
    const float* __restrict__ A, const float* __restrict__ W,
    const float* __restrict__ bias, float* __restrict__ C,
    int dosilu, int attlay)
{
    extern __shared__ float sm[];
    const uint32_t sb = smem_u32(sm);
    const int t = threadIdx.x;
    const int lane = t & 31, wid = t >> 5;
    const int wm = wid >> 2, wn = wid & 3;     // 2 x 4 warp grid
    const int m0 = blockIdx.y * BM;
    const int n0 = blockIdx.x * BN;
    const int g = lane >> 2, tc = lane & 3;

    float acc[4][4][4];
#pragma unroll
    for (int i = 0; i < 4; ++i)
#pragma unroll
        for (int j = 0; j < 4; ++j)
#pragma unroll
            for (int e = 0; e < 4; ++e) acc[i][j][e] = 0.f;

    const float* Abase = A + (size_t)m0 * DDIM;
    const float* Wbase = W + (size_t)n0 * DDIM;

    auto load_chunk = [&](int stage, int kc) {
        const uint32_t abase = sb + (uint32_t)(stage * STAGE_FLOATS) * 4u;
        const uint32_t bbase = abase + A_FLOATS * 4u;
        const int k0 = kc * BKK;
#pragma unroll
        for (int i = 0; i < 4; ++i) {           // A: 1024 x 16B
            int idx = t + 256 * i;
            int row = idx >> 3, seg = idx & 7;
            cp16(abase + (uint32_t)(row * STRD + seg * 4) * 4u,
                 Abase + (size_t)row * DDIM + k0 + seg * 4);
        }
#pragma unroll
        for (int i = 0; i < 4; ++i) {           // B: 1024 x 16B
            int idx = t + 256 * i;
            int row = idx >> 3, seg = idx & 7;
            cp16(bbase + (uint32_t)(row * STRD + seg * 4) * 4u,
                 Wbase + (size_t)row * DDIM + k0 + seg * 4);
        }
    };

    // prologue
#pragma unroll
    for (int s = 0; s < GSTAGES; ++s) { load_chunk(s, s); cp_commit(); }

    int cur = 0;
    for (int kc = 0; kc < KCH; ++kc) {
        CP_WAIT(GSTAGES - 1);
        __syncthreads();

        const float* sA = sm + cur * STAGE_FLOATS;
        const float* sB = sA + A_FLOATS;
#pragma unroll
        for (int ks = 0; ks < 4; ++ks) {
            const int k0 = ks * 8;
            // B fragments hi/lo (8 elems)
            uint32_t bh_[4][2], bl_[4][2];
#pragma unroll
            for (int nt = 0; nt < 4; ++nt) {
                const float* p = sB + (wn * 32 + nt * 8 + g) * STRD + k0 + tc;
                split_tf32(p[0], bh_[nt][0], bl_[nt][0]);
                split_tf32(p[4], bh_[nt][1], bl_[nt][1]);
            }
#pragma unroll
            for (int mt = 0; mt < 4; ++mt) {
                const float* p = sA + (wm * 64 + mt * 16 + g) * STRD + k0 + tc;
                uint32_t ah[4], al[4];
                split_tf32(p[0],            ah[0], al[0]);
                split_tf32(p[8 * STRD],     ah[1], al[1]);
                split_tf32(p[4],            ah[2], al[2]);
                split_tf32(p[8 * STRD + 4], ah[3], al[3]);
#pragma unroll
                for (int nt = 0; nt < 4; ++nt) {
                    mma8(acc[mt][nt], ah, bl_[nt]);   // hi*lo
                    mma8(acc[mt][nt], al, bh_[nt]);   // lo*hi
                    mma8(acc[mt][nt], ah, bh_[nt]);   // hi*hi
                }
            }
        }
        __syncthreads();

        if (kc + GSTAGES < KCH) load_chunk(cur, kc + GSTAGES);
        cp_commit();

        cur = (cur == GSTAGES - 1) ? 0 : cur + 1;
    }

    // ---- epilogue ----
#pragma unroll
    for (int mt = 0; mt < 4; ++mt) {
        const int mrow = m0 + wm * 64 + mt * 16 + g;
#pragma unroll
        for (int nt = 0; nt < 4; ++nt) {
            const int n = n0 + wn * 32 + nt * 8 + tc * 2;
#pragma unroll
            for (int half = 0; half < 2; ++half) {
                const int m = mrow + half * 8;
                float v0 = acc[mt][nt][half * 2 + 0] + bias[n];
                float v1 = acc[mt][nt][half * 2 + 1] + bias[n + 1];
                if (dosilu) {
                    v0 = v0 / (1.f + expf(-v0));
                    v1 = v1 / (1.f + expf(-v1));
                }
                float2 o; o.x = v0; o.y = v1;
                if (attlay) {
                    int b  = m >> 11;
                    int l  = m & 2047;
                    int h  = n >> 6;
                    int dd = n & 63;
                    *(float2*)&C[(((size_t)(b * HH + h)) * LL + l) * DH + dd] = o;
                } else {
                    *(float2*)&C[(size_t)m * DDIM + n] = o;
                }
            }
        }
    }
}

// ---------------- Phase A: per-chunk kv outer product + ksum ----------------
__global__ __launch_bounds__(256) void chunk_stats()
{
    __shared__ float ks[32*64];
    __shared__ float vs[32*64];

    const int bid = blockIdx.x;
    const float* kb = g_k + (size_t)bid * (CH*DH);
    const float* vb = g_v + (size_t)bid * (CH*DH);
    const int t  = threadIdx.x;
    const int td = t >> 4;
    const int te = t & 15;

    float acc[4][4];
#pragma unroll
    for (int i = 0; i < 4; ++i)
#pragma unroll
        for (int j = 0; j < 4; ++j) acc[i][j] = 0.f;
    float zacc = 0.f;

    for (int cb = 0; cb < 4; ++cb) {
#pragma unroll
        for (int r = 0; r < 2; ++r) {
            int f = t*2 + r;
            *(float4*)&ks[f*4] = *(const float4*)(kb + cb*2048 + f*4);
            *(float4*)&vs[f*4] = *(const float4*)(vb + cb*2048 + f*4);
        }
        __syncthreads();
#pragma unroll 8
        for (int c = 0; c < 32; ++c) {
            float a[4], b[4];
            *(float4*)a = *(const float4*)&ks[c*64 + td*4];
            *(float4*)b = *(const float4*)&vs[c*64 + te*4];
#pragma unroll
            for (int i = 0; i < 4; ++i)
#pragma unroll
                for (int j = 0; j < 4; ++j)
                    acc[i][j] = fmaf(a[i], b[j], acc[i][j]);
        }
        if (t < 64) {
#pragma unroll 8
            for (int c = 0; c < 32; ++c) zacc += ks[c*64 + t];
        }
        __syncthreads();
    }

    float* Sp = g_S + (size_t)bid * (DH*DH);
#pragma unroll
    for (int i = 0; i < 4; ++i)
#pragma unroll
        for (int j = 0; j < 4; ++j)
            Sp[(td*4 + i)*DH + te*4 + j] = acc[i][j];
    if (t < 64) g_z[(size_t)bid*DH + t] = zacc;
}

// ---------------- Phase B: exclusive scan over chunks ----------------
__global__ __launch_bounds__(256) void scan_chunks()
{
    const int bh = blockIdx.x;
    const int t  = threadIdx.x;
    for (int idx = t; idx < DH*DH; idx += 256) {
        float accv = 0.f;
#pragma unroll
        for (int nn = 0; nn < NC; ++nn) {
            float* p = g_S + ((size_t)(bh*NC + nn))*(DH*DH) + idx;
            float tv = *p; *p = accv; accv += tv;
        }
    }
    if (t < DH) {
        float accv = 0.f;
#pragma unroll
        for (int nn = 0; nn < NC; ++nn) {
            float* p = g_z + ((size_t)(bh*NC + nn))*DH + t;
            float tv = *p; *p = accv; accv += tv;
        }
    }
}

// ---------------- Phase C: intra-chunk causal attention ----------------
#define SMEMC_FLOATS (64*136 + 64*136 + 128*64 + 64*64 + 64 + 128 + 128*132)
__global__ __launch_bounds__(256) void intra_chunk()
{
    extern __shared__ float smc[];
    float* qT   = smc;
    float* kT   = qT + 64*136;
    float* vs   = kT + 64*136;
    float* Ss   = vs + 128*64;
    float* zs   = Ss + 64*64;
    float* rden = zs + 64;
    float* ms   = rden + 128;

    const int bid = blockIdx.x;
    const int t   = threadIdx.x;
    const float* qb = g_q + (size_t)bid * (CH*DH);
    const float* kb = g_k + (size_t)bid * (CH*DH);
    const float* vb = g_v + (size_t)bid * (CH*DH);

    {
        int dd = t & 63;
        int ih = t >> 6;
#pragma unroll 8
        for (int ii = 0; ii < 32; ++ii) {
            int i = ih*32 + ii;
            qT[dd*136 + i] = qb[i*DH + dd];
            kT[dd*136 + i] = kb[i*DH + dd];
        }
    }
#pragma unroll
    for (int r = 0; r < 8; ++r) {
        int f = t + 256*r;
        *(float4*)&vs[f*4] = *(const float4*)(vb + f*4);
    }
    {
        const float* Sp = g_S + (size_t)bid * (DH*DH);
#pragma unroll
        for (int r = 0; r < 4; ++r) {
            int f = t + 256*r;
            *(float4*)&Ss[f*4] = *(const float4*)(Sp + f*4);
        }
    }
    if (t < 64) zs[t] = g_z[(size_t)bid*DH + t];
    __syncthreads();

    const int ty = t >> 4, tx = t & 15;
    const int i0 = ty*8, j0 = tx*8;

    float acc[8][8];
#pragma unroll
    for (int i = 0; i < 8; ++i)
#pragma unroll
        for (int j = 0; j < 8; ++j) acc[i][j] = 0.f;

    if (j0 <= i0 + 7) {
#pragma unroll 4
        for (int c = 0; c < 64; ++c) {
            float a[8], b[8];
            *(float4*)(a)     = *(const float4*)&qT[c*136 + i0];
            *(float4*)(a + 4) = *(const float4*)&qT[c*136 + i0 + 4];
            *(float4*)(b)     = *(const float4*)&kT[c*136 + j0];
            *(float4*)(b + 4) = *(const float4*)&kT[c*136 + j0 + 4];
#pragma unroll
            for (int i = 0; i < 8; ++i)
#pragma unroll
                for (int j = 0; j < 8; ++j)
                    acc[i][j] = fmaf(a[i], b[j], acc[i][j]);
        }
    }
#pragma unroll
    for (int i = 0; i < 8; ++i)
#pragma unroll
        for (int j = 0; j < 8; ++j)
            ms[(i0+i)*132 + j0 + j] = (j0 + j <= i0 + i) ? acc[i][j] : 0.f;
    __syncthreads();

    if (t < 128) {
        int i = t;
        float s = 0.f;
#pragma unroll 8
        for (int j = 0; j < 128; ++j) s += ms[i*132 + j];
#pragma unroll 8
        for (int dd = 0; dd < 64; ++dd) s += qT[dd*136 + i] * zs[dd];
        rden[i] = 1.f / fmaxf(s, 0.001f);
    }
    __syncthreads();

    const int e0 = tx*4;
    float o[8][4];
#pragma unroll
    for (int i = 0; i < 8; ++i)
#pragma unroll
        for (int e = 0; e < 4; ++e) o[i][e] = 0.f;

#pragma unroll 4
    for (int j = 0; j < 128; ++j) {
        float vf[4];
        *(float4*)vf = *(const float4*)&vs[j*64 + e0];
#pragma unroll
        for (int i = 0; i < 8; ++i) {
            float mv = ms[(i0+i)*132 + j];
            o[i][0] = fmaf(mv, vf[0], o[i][0]);
            o[i][1] = fmaf(mv, vf[1], o[i][1]);
            o[i][2] = fmaf(mv, vf[2], o[i][2]);
            o[i][3] = fmaf(mv, vf[3], o[i][3]);
        }
    }
#pragma unroll 4
    for (int dd = 0; dd < 64; ++dd) {
        float sf[4];
        *(float4*)sf = *(const float4*)&Ss[dd*64 + e0];
#pragma unroll
        for (int i = 0; i < 8; ++i) {
            float qv = qT[dd*136 + i0 + i];
            o[i][0] = fmaf(qv, sf[0], o[i][0]);
            o[i][1] = fmaf(qv, sf[1], o[i][1]);
            o[i][2] = fmaf(qv, sf[2], o[i][2]);
            o[i][3] = fmaf(qv, sf[3], o[i][3]);
        }
    }

    const int bh = bid >> 4, n = bid & 15;
    const int b = bh >> 4, h = bh & 15;
#pragma unroll
    for (int i = 0; i < 8; ++i) {
        float rd = rden[i0 + i];
        int l = n*CH + i0 + i;
#pragma unroll
        for (int e = 0; e < 4; ++e)
            g_att[((size_t)(b*LL + l))*DDIM + h*DH + e0 + e] = o[i][e] * rd;
    }
}

// ---------------- launch ----------------
extern "C" void kernel_launch(void* const* d_in, const int* in_sizes, int n_in,
                              void* d_out, int out_size)
{
    const float* x  = (const float*)d_in[0];
    const float* Wq = (const float*)d_in[1];
    const float* bq = (const float*)d_in[2];
    const float* Wk = (const float*)d_in[3];
    const float* bk = (const float*)d_in[4];
    const float* Wv = (const float*)d_in[5];
    const float* bv = (const float*)d_in[6];
    const float* Wo = (const float*)d_in[7];
    const float* bo = (const float*)d_in[8];
    float* out = (float*)d_out;

    float *qp, *kp, *vp, *attp;
    cudaGetSymbolAddress((void**)&qp,  g_q);
    cudaGetSymbolAddress((void**)&kp,  g_k);
    cudaGetSymbolAddress((void**)&vp,  g_v);
    cudaGetSymbolAddress((void**)&attp, g_att);

    cudaFuncSetAttribute(gemm_tc, cudaFuncAttributeMaxDynamicSharedMemorySize,
                         SMEM_GEMM_BYTES);
    cudaFuncSetAttribute(intra_chunk, cudaFuncAttributeMaxDynamicSharedMemorySize,
                         SMEMC_FLOATS * (int)sizeof(float));

    dim3 gg(DDIM/BN, BLROWS/BM);   // (8, 64)
    dim3 bb(256);

    gemm_tc<<<gg, bb, SMEM_GEMM_BYTES>>>(x, Wq, bq, qp, 1, 1);
    gemm_tc<<<gg, bb, SMEM_GEMM_BYTES>>>(x, Wk, bk, kp, 1, 1);
    gemm_tc<<<gg, bb, SMEM_GEMM_BYTES>>>(x, Wv, bv, vp, 0, 1);

    chunk_stats<<<BH*NC, 256>>>();
    scan_chunks<<<BH, 256>>>();
    intra_chunk<<<BH*NC, 256, SMEMC_FLOATS * sizeof(float)>>>();

    gemm_tc<<<gg, bb, SMEM_GEMM_BYTES>>>(attp, Wo, bo, out, 0, 0);
}

// round 5
// speedup vs baseline: 2.1685x; 1.3298x over previous
#include <cuda_runtime.h>
#include <cstdint>
#include <math.h>

// Problem constants
#define BB 4
#define LL 2048
#define DDIM 1024
#define HH 16
#define DH 64
#define CH 128
#define NC 16
#define BH (BB*HH)        // 64
#define BLROWS (BB*LL)    // 8192

// ---------------- scratch (no allocations allowed) ----------------
__device__ float g_q[BB*HH*LL*DH];        // (B,H,L,d)
__device__ float g_k[BB*HH*LL*DH];
__device__ float g_v[BB*HH*LL*DH];
__device__ float g_att[BB*LL*DDIM];       // (B,L,D)
__device__ float g_S[BB*HH*NC*DH*DH];
__device__ float g_z[BB*HH*NC*DH];

// =======================================================================
// TF32 mma.sync GEMM:  C = A @ W^T + bias (A: M x K, W: N x K, row-major)
// Tile 128x128, BK=32, 3-stage cp.async pipeline, 8 warps (2x4), warp 64x32.
// NSPLIT=3: Markidis hi/lo split (~21-bit mantissa) for Q/K (den-amplified paths)
// NSPLIT=1: plain tf32 for V / Wo (linear error propagation)
// =======================================================================
#define BM 128
#define BN 128
#define BKK 32
#define KCH (DDIM/BKK)        // 32
#define GSTAGES 3
#define STRD 36               // floats per row (stride % 32 == 4 -> conflict-free frags)
#define A_FLOATS (BM*STRD)    // 4608
#define STAGE_FLOATS (2*A_FLOATS)   // 9216 (A then B)
#define SMEM_GEMM_BYTES (GSTAGES*STAGE_FLOATS*4)   // 110592

__device__ __forceinline__ void cp16(uint32_t dst, const void* src) {
    asm volatile("cp.async.cg.shared.global [%0], [%1], 16;" :: "r"(dst), "l"(src));
}
__device__ __forceinline__ uint32_t smem_u32(const void* p) {
    uint32_t a;
    asm("{ .reg .u64 t; cvta.to.shared.u64 t, %1; cvt.u32.u64 %0, t; }" : "=r"(a) : "l"(p));
    return a;
}
__device__ __forceinline__ void cp_commit() {
    asm volatile("cp.async.commit_group;");
}
#define CP_WAIT(n) asm volatile("cp.async.wait_group %0;" :: "n"(n))

__device__ __forceinline__ uint32_t to_tf32(float f) {
    uint32_t r;
    asm("cvt.rna.tf32.f32 %0, %1;" : "=r"(r) : "f"(f));
    return r;
}
__device__ __forceinline__ void split_tf32(float f, uint32_t& hi, uint32_t& lo) {
    hi = to_tf32(f);
    lo = to_tf32(f - __uint_as_float(hi));
}
__device__ __forceinline__ void mma8(float* d, const uint32_t* a, const uint32_t* b) {
    asm volatile(
        "mma.sync.aligned.m16n8k8.row.col.f32.tf32.tf32.f32 "
        "{%0,%1,%2,%3}, {%4,%5,%6,%7}, {%8,%9}, {%0,%1,%2,%3};"
        : "+f"(d[0]), "+f"(d[1]), "+f"(d[2]), "+f"(d[3])
        : "r"(a[0]), "r"(a[1]), "r"(a[2]), "r"(a[3]), "r"(b[0]), "r"(b[1]));
}

// grid: (DDIM/BN, BLROWS/BM) = (8, 64), 256 threads
template<int NSPLIT, int DOSILU, int ATTLAY>
__global__ void __launch_bounds__(256, 2) gemm_tc(
    const float* __restrict__ A, const float* __restrict__ W,
    const float* __restrict__ bias, float* __restrict__ C)
{
    extern __shared__ float sm[];
    const uint32_t sb = smem_u32(sm);
    const int t = threadIdx.x;
    const int lane = t & 31, wid = t >> 5;
    const int wm = wid >> 2, wn = wid & 3;     // 2 x 4 warp grid
    const int m0 = blockIdx.y * BM;
    const int n0 = blockIdx.x * BN;
    const int g = lane >> 2, tc = lane & 3;

    float acc[4][4][4];
#pragma unroll
    for (int i = 0; i < 4; ++i)
#pragma unroll
        for (int j = 0; j < 4; ++j)
#pragma unroll
            for (int e = 0; e < 4; ++e) acc[i][j][e] = 0.f;

    const float* Abase = A + (size_t)m0 * DDIM;
    const float* Wbase = W + (size_t)n0 * DDIM;

    auto load_chunk = [&](int stage, int kc) {
        const uint32_t abase = sb + (uint32_t)(stage * STAGE_FLOATS) * 4u;
        const uint32_t bbase = abase + A_FLOATS * 4u;
        const int k0 = kc * BKK;
#pragma unroll
        for (int i = 0; i < 4; ++i) {           // A: 1024 x 16B
            int idx = t + 256 * i;
            int row = idx >> 3, seg = idx & 7;
            cp16(abase + (uint32_t)(row * STRD + seg * 4) * 4u,
                 Abase + (size_t)row * DDIM + k0 + seg * 4);
        }
#pragma unroll
        for (int i = 0; i < 4; ++i) {           // B: 1024 x 16B
            int idx = t + 256 * i;
            int row = idx >> 3, seg = idx & 7;
            cp16(bbase + (uint32_t)(row * STRD + seg * 4) * 4u,
                 Wbase + (size_t)row * DDIM + k0 + seg * 4);
        }
    };

    // prologue
#pragma unroll
    for (int s = 0; s < GSTAGES; ++s) { load_chunk(s, s); cp_commit(); }

    int cur = 0;
    for (int kc = 0; kc < KCH; ++kc) {
        CP_WAIT(GSTAGES - 1);
        __syncthreads();

        const float* sA = sm + cur * STAGE_FLOATS;
        const float* sB = sA + A_FLOATS;
#pragma unroll
        for (int ks = 0; ks < 4; ++ks) {
            const int k0 = ks * 8;
            uint32_t bh_[4][2], bl_[4][2];
#pragma unroll
            for (int nt = 0; nt < 4; ++nt) {
                const float* p = sB + (wn * 32 + nt * 8 + g) * STRD + k0 + tc;
                if (NSPLIT == 3) {
                    split_tf32(p[0], bh_[nt][0], bl_[nt][0]);
                    split_tf32(p[4], bh_[nt][1], bl_[nt][1]);
                } else {
                    bh_[nt][0] = to_tf32(p[0]);
                    bh_[nt][1] = to_tf32(p[4]);
                }
            }
#pragma unroll
            for (int mt = 0; mt < 4; ++mt) {
                const float* p = sA + (wm * 64 + mt * 16 + g) * STRD + k0 + tc;
                uint32_t ah[4], al[4];
                if (NSPLIT == 3) {
                    split_tf32(p[0],            ah[0], al[0]);
                    split_tf32(p[8 * STRD],     ah[1], al[1]);
                    split_tf32(p[4],            ah[2], al[2]);
                    split_tf32(p[8 * STRD + 4], ah[3], al[3]);
                } else {
                    ah[0] = to_tf32(p[0]);
                    ah[1] = to_tf32(p[8 * STRD]);
                    ah[2] = to_tf32(p[4]);
                    ah[3] = to_tf32(p[8 * STRD + 4]);
                }
#pragma unroll
                for (int nt = 0; nt < 4; ++nt) {
                    if (NSPLIT == 3) {
                        mma8(acc[mt][nt], ah, bl_[nt]);   // hi*lo
                        mma8(acc[mt][nt], al, bh_[nt]);   // lo*hi
                    }
                    mma8(acc[mt][nt], ah, bh_[nt]);       // hi*hi
                }
            }
        }
        __syncthreads();

        if (kc + GSTAGES < KCH) load_chunk(cur, kc + GSTAGES);
        cp_commit();

        cur = (cur == GSTAGES - 1) ? 0 : cur + 1;
    }

    // ---- epilogue ----
#pragma unroll
    for (int mt = 0; mt < 4; ++mt) {
        const int mrow = m0 + wm * 64 + mt * 16 + g;
#pragma unroll
        for (int nt = 0; nt < 4; ++nt) {
            const int n = n0 + wn * 32 + nt * 8 + tc * 2;
#pragma unroll
            for (int half = 0; half < 2; ++half) {
                const int m = mrow + half * 8;
                float v0 = acc[mt][nt][half * 2 + 0] + bias[n];
                float v1 = acc[mt][nt][half * 2 + 1] + bias[n + 1];
                if (DOSILU) {
                    v0 = v0 / (1.f + expf(-v0));
                    v1 = v1 / (1.f + expf(-v1));
                }
                float2 o; o.x = v0; o.y = v1;
                if (ATTLAY) {
                    int b  = m >> 11;
                    int l  = m & 2047;
                    int h  = n >> 6;
                    int dd = n & 63;
                    *(float2*)&C[(((size_t)(b * HH + h)) * LL + l) * DH + dd] = o;
                } else {
                    *(float2*)&C[(size_t)m * DDIM + n] = o;
                }
            }
        }
    }
}

// ---------------- Phase A: per-chunk kv outer product + ksum ----------------
__global__ __launch_bounds__(256) void chunk_stats()
{
    __shared__ float ks[32*64];
    __shared__ float vs[32*64];

    const int bid = blockIdx.x;
    const float* kb = g_k + (size_t)bid * (CH*DH);
    const float* vb = g_v + (size_t)bid * (CH*DH);
    const int t  = threadIdx.x;
    const int td = t >> 4;
    const int te = t & 15;

    float acc[4][4];
#pragma unroll
    for (int i = 0; i < 4; ++i)
#pragma unroll
        for (int j = 0; j < 4; ++j) acc[i][j] = 0.f;
    float zacc = 0.f;

    for (int cb = 0; cb < 4; ++cb) {
#pragma unroll
        for (int r = 0; r < 2; ++r) {
            int f = t*2 + r;
            *(float4*)&ks[f*4] = *(const float4*)(kb + cb*2048 + f*4);
            *(float4*)&vs[f*4] = *(const float4*)(vb + cb*2048 + f*4);
        }
        __syncthreads();
#pragma unroll 8
        for (int c = 0; c < 32; ++c) {
            float a[4], b[4];
            *(float4*)a = *(const float4*)&ks[c*64 + td*4];
            *(float4*)b = *(const float4*)&vs[c*64 + te*4];
#pragma unroll
            for (int i = 0; i < 4; ++i)
#pragma unroll
                for (int j = 0; j < 4; ++j)
                    acc[i][j] = fmaf(a[i], b[j], acc[i][j]);
        }
        if (t < 64) {
#pragma unroll 8
            for (int c = 0; c < 32; ++c) zacc += ks[c*64 + t];
        }
        __syncthreads();
    }

    float* Sp = g_S + (size_t)bid * (DH*DH);
#pragma unroll
    for (int i = 0; i < 4; ++i)
#pragma unroll
        for (int j = 0; j < 4; ++j)
            Sp[(td*4 + i)*DH + te*4 + j] = acc[i][j];
    if (t < 64) g_z[(size_t)bid*DH + t] = zacc;
}

// ---------------- Phase B: exclusive scan over chunks ----------------
__global__ __launch_bounds__(256) void scan_chunks()
{
    const int bh = blockIdx.x;
    const int t  = threadIdx.x;
    for (int idx = t; idx < DH*DH; idx += 256) {
        float accv = 0.f;
#pragma unroll
        for (int nn = 0; nn < NC; ++nn) {
            float* p = g_S + ((size_t)(bh*NC + nn))*(DH*DH) + idx;
            float tv = *p; *p = accv; accv += tv;
        }
    }
    if (t < DH) {
        float accv = 0.f;
#pragma unroll
        for (int nn = 0; nn < NC; ++nn) {
            float* p = g_z + ((size_t)(bh*NC + nn))*DH + t;
            float tv = *p; *p = accv; accv += tv;
        }
    }
}

// ---------------- Phase C: intra-chunk causal attention ----------------
#define SMEMC_FLOATS (64*136 + 64*136 + 128*64 + 64*64 + 64 + 128 + 128*132)
__global__ __launch_bounds__(256) void intra_chunk()
{
    extern __shared__ float smc[];
    float* qT   = smc;
    float* kT   = qT + 64*136;
    float* vs   = kT + 64*136;
    float* Ss   = vs + 128*64;
    float* zs   = Ss + 64*64;
    float* rden = zs + 64;
    float* ms   = rden + 128;

    const int bid = blockIdx.x;
    const int t   = threadIdx.x;
    const float* qb = g_q + (size_t)bid * (CH*DH);
    const float* kb = g_k + (size_t)bid * (CH*DH);
    const float* vb = g_v + (size_t)bid * (CH*DH);

    {
        int dd = t & 63;
        int ih = t >> 6;
#pragma unroll 8
        for (int ii = 0; ii < 32; ++ii) {
            int i = ih*32 + ii;
            qT[dd*136 + i] = qb[i*DH + dd];
            kT[dd*136 + i] = kb[i*DH + dd];
        }
    }
#pragma unroll
    for (int r = 0; r < 8; ++r) {
        int f = t + 256*r;
        *(float4*)&vs[f*4] = *(const float4*)(vb + f*4);
    }
    {
        const float* Sp = g_S + (size_t)bid * (DH*DH);
#pragma unroll
        for (int r = 0; r < 4; ++r) {
            int f = t + 256*r;
            *(float4*)&Ss[f*4] = *(const float4*)(Sp + f*4);
        }
    }
    if (t < 64) zs[t] = g_z[(size_t)bid*DH + t];
    __syncthreads();

    const int ty = t >> 4, tx = t & 15;
    const int i0 = ty*8, j0 = tx*8;

    float acc[8][8];
#pragma unroll
    for (int i = 0; i < 8; ++i)
#pragma unroll
        for (int j = 0; j < 8; ++j) acc[i][j] = 0.f;

    if (j0 <= i0 + 7) {
#pragma unroll 4
        for (int c = 0; c < 64; ++c) {
            float a[8], b[8];
            *(float4*)(a)     = *(const float4*)&qT[c*136 + i0];
            *(float4*)(a + 4) = *(const float4*)&qT[c*136 + i0 + 4];
            *(float4*)(b)     = *(const float4*)&kT[c*136 + j0];
            *(float4*)(b + 4) = *(const float4*)&kT[c*136 + j0 + 4];
#pragma unroll
            for (int i = 0; i < 8; ++i)
#pragma unroll
                for (int j = 0; j < 8; ++j)
                    acc[i][j] = fmaf(a[i], b[j], acc[i][j]);
        }
    }
#pragma unroll
    for (int i = 0; i < 8; ++i)
#pragma unroll
        for (int j = 0; j < 8; ++j)
            ms[(i0+i)*132 + j0 + j] = (j0 + j <= i0 + i) ? acc[i][j] : 0.f;
    __syncthreads();

    if (t < 128) {
        int i = t;
        float s = 0.f;
#pragma unroll 8
        for (int j = 0; j < 128; ++j) s += ms[i*132 + j];
#pragma unroll 8
        for (int dd = 0; dd < 64; ++dd) s += qT[dd*136 + i] * zs[dd];
        rden[i] = 1.f / fmaxf(s, 0.001f);
    }
    __syncthreads();

    const int e0 = tx*4;
    float o[8][4];
#pragma unroll
    for (int i = 0; i < 8; ++i)
#pragma unroll
        for (int e = 0; e < 4; ++e) o[i][e] = 0.f;

#pragma unroll 4
    for (int j = 0; j < 128; ++j) {
        float vf[4];
        *(float4*)vf = *(const float4*)&vs[j*64 + e0];
#pragma unroll
        for (int i = 0; i < 8; ++i) {
            float mv = ms[(i0+i)*132 + j];
            o[i][0] = fmaf(mv, vf[0], o[i][0]);
            o[i][1] = fmaf(mv, vf[1], o[i][1]);
            o[i][2] = fmaf(mv, vf[2], o[i][2]);
            o[i][3] = fmaf(mv, vf[3], o[i][3]);
        }
    }
#pragma unroll 4
    for (int dd = 0; dd < 64; ++dd) {
        float sf[4];
        *(float4*)sf = *(const float4*)&Ss[dd*64 + e0];
#pragma unroll
        for (int i = 0; i < 8; ++i) {
            float qv = qT[dd*136 + i0 + i];
            o[i][0] = fmaf(qv, sf[0], o[i][0]);
            o[i][1] = fmaf(qv, sf[1], o[i][1]);
            o[i][2] = fmaf(qv, sf[2], o[i][2]);
            o[i][3] = fmaf(qv, sf[3], o[i][3]);
        }
    }

    const int bh = bid >> 4, n = bid & 15;
    const int b = bh >> 4, h = bh & 15;
#pragma unroll
    for (int i = 0; i < 8; ++i) {
        float rd = rden[i0 + i];
        int l = n*CH + i0 + i;
#pragma unroll
        for (int e = 0; e < 4; ++e)
            g_att[((size_t)(b*LL + l))*DDIM + h*DH + e0 + e] = o[i][e] * rd;
    }
}

// ---------------- launch ----------------
extern "C" void kernel_launch(void* const* d_in, const int* in_sizes, int n_in,
                              void* d_out, int out_size)
{
    const float* x  = (const float*)d_in[0];
    const float* Wq = (const float*)d_in[1];
    const float* bq = (const float*)d_in[2];
    const float* Wk = (const float*)d_in[3];
    const float* bk = (const float*)d_in[4];
    const float* Wv = (const float*)d_in[5];
    const float* bv = (const float*)d_in[6];
    const float* Wo = (const float*)d_in[7];
    const float* bo = (const float*)d_in[8];
    float* out = (float*)d_out;

    float *qp, *kp, *vp, *attp;
    cudaGetSymbolAddress((void**)&qp,  g_q);
    cudaGetSymbolAddress((void**)&kp,  g_k);
    cudaGetSymbolAddress((void**)&vp,  g_v);
    cudaGetSymbolAddress((void**)&attp, g_att);

    cudaFuncSetAttribute(gemm_tc<3,1,1>, cudaFuncAttributeMaxDynamicSharedMemorySize,
                         SMEM_GEMM_BYTES);
    cudaFuncSetAttribute(gemm_tc<1,0,1>, cudaFuncAttributeMaxDynamicSharedMemorySize,
                         SMEM_GEMM_BYTES);
    cudaFuncSetAttribute(gemm_tc<1,0,0>, cudaFuncAttributeMaxDynamicSharedMemorySize,
                         SMEM_GEMM_BYTES);
    cudaFuncSetAttribute(intra_chunk, cudaFuncAttributeMaxDynamicSharedMemorySize,
                         SMEMC_FLOATS * (int)sizeof(float));

    dim3 gg(DDIM/BN, BLROWS/BM);   // (8, 64)
    dim3 bb(256);

    gemm_tc<3,1,1><<<gg, bb, SMEM_GEMM_BYTES>>>(x, Wq, bq, qp);
    gemm_tc<3,1,1><<<gg, bb, SMEM_GEMM_BYTES>>>(x, Wk, bk, kp);
    gemm_tc<1,0,1><<<gg, bb, SMEM_GEMM_BYTES>>>(x, Wv, bv, vp);

    chunk_stats<<<BH*NC, 256>>>();
    scan_chunks<<<BH, 256>>>();
    intra_chunk<<<BH*NC, 256, SMEMC_FLOATS * sizeof(float)>>>();

    gemm_tc<1,0,0><<<gg, bb, SMEM_GEMM_BYTES>>>(attp, Wo, bo, out);
}